// round 1
// baseline (speedup 1.0000x reference)
#include <cuda_runtime.h>
#include <math.h>
#include <stdint.h>

// Problem constants (match reference setup_inputs)
#define BDIM      8
#define NTOK      8192
#define TOTT      (BDIM * NTOK)
#define NUMHEAVY  1024
#define NITERS    50

// Scratch (no cudaMalloc allowed)
__device__ float g_s[TOTT];
__device__ float g_inv[TOTT];                 // 32/||x_row|| (rmsnorm scale, gamma applied separately)
__device__ int   g_sel[BDIM * NUMHEAVY];
__device__ float g_hidden[33554432];          // max(65536*512, 8192*4096) floats = 128 MiB

// ---------------------------------------------------------------------------
// Kernel 1: per-token router logit s = x . routing_token and rmsnorm scale
// one warp per token
// ---------------------------------------------------------------------------
__global__ void dot_norm_kernel(const float* __restrict__ x,
                                const float* __restrict__ rt,
                                float* __restrict__ s_out,
                                float* __restrict__ inv_out,
                                int dim)
{
    int gwarp = (blockIdx.x * blockDim.x + threadIdx.x) >> 5;   // token id
    int lane  = threadIdx.x & 31;
    const float* xr = x + (size_t)gwarp * dim;
    float d = 0.f, q = 0.f;
    for (int k = lane; k < dim; k += 32) {
        float v = xr[k];
        d += v * rt[k];
        q += v * v;
    }
    #pragma unroll
    for (int o = 16; o; o >>= 1) {
        d += __shfl_xor_sync(0xffffffffu, d, o);
        q += __shfl_xor_sync(0xffffffffu, q, o);
    }
    if (lane == 0) {
        s_out[gwarp]   = d;
        float nrm = fmaxf(sqrtf(q), 1e-12f);
        inv_out[gwarp] = sqrtf((float)dim) / nrm;
    }
}

// ---------------------------------------------------------------------------
// Kernel 2: coor_descent (50 iters) + exact top-k with jax tie-breaking.
// One block (1024 threads) per batch row. Dynamic smem:
//   float ssh[NTOK] | uint64 keys[NTOK] | float red[32]
// ---------------------------------------------------------------------------
__global__ void router_kernel(const float* __restrict__ s_in,
                              float logk,
                              int* __restrict__ sel)
{
    extern __shared__ unsigned char smraw[];
    float* ssh = (float*)smraw;
    unsigned long long* keys = (unsigned long long*)(smraw + NTOK * sizeof(float));
    float* red = (float*)(smraw + NTOK * sizeof(float) + NTOK * sizeof(unsigned long long));

    const int tid = threadIdx.x;
    const int bt  = blockIdx.x;
    const int PER = NTOK / 1024;            // 8
    const float* srow = s_in + (size_t)bt * NTOK;

    for (int w = 0; w < PER; w++) ssh[tid + w * 1024] = srow[tid + w * 1024];
    __syncthreads();

    // iteration 1: s + b0 == 0 exactly -> logsumexp = log(n)
    float a = logk - logf((float)NTOK);

    for (int it = 1; it < NITERS; it++) {
        // arg_i = s_i - max(s_i + a, 0)   (== s + b, replicating jax fp ops)
        float args[8];
        float lm = -INFINITY;
        #pragma unroll
        for (int w = 0; w < 8; w++) {
            float sv = ssh[tid + w * 1024];
            float t  = sv + a;
            float ar = sv - fmaxf(t, 0.0f);
            args[w] = ar;
            lm = fmaxf(lm, ar);
        }
        #pragma unroll
        for (int o = 16; o; o >>= 1) lm = fmaxf(lm, __shfl_xor_sync(0xffffffffu, lm, o));
        if ((tid & 31) == 0) red[tid >> 5] = lm;
        __syncthreads();
        if (tid < 32) {
            float v = red[tid];
            #pragma unroll
            for (int o = 16; o; o >>= 1) v = fmaxf(v, __shfl_xor_sync(0xffffffffu, v, o));
            if (tid == 0) red[0] = v;
        }
        __syncthreads();
        float m = red[0];
        __syncthreads();                    // everyone read red[0] before reuse

        float ls = 0.f;
        #pragma unroll
        for (int w = 0; w < 8; w++) ls += expf(args[w] - m);
        #pragma unroll
        for (int o = 16; o; o >>= 1) ls += __shfl_xor_sync(0xffffffffu, ls, o);
        if ((tid & 31) == 0) red[tid >> 5] = ls;
        __syncthreads();
        if (tid < 32) {
            float v = red[tid];
            #pragma unroll
            for (int o = 16; o; o >>= 1) v += __shfl_xor_sync(0xffffffffu, v, o);
            if (tid == 0) red[0] = v;
        }
        __syncthreads();
        float ssum = red[0];
        __syncthreads();

        a = logk - (logf(ssum) + m);
    }

    // scores -> sort keys (descending score, ascending index == jax top_k order)
    #pragma unroll
    for (int w = 0; w < 8; w++) {
        int i = tid + w * 1024;
        float u  = ssh[i] + a;
        float sc = (u > 0.0f) ? 1.0f : expf(u);
        unsigned sb = __float_as_uint(sc) ^ 0xffffffffu;  // score >= 0 -> monotone
        keys[i] = ((unsigned long long)sb << 32) | (unsigned)i;
    }
    __syncthreads();

    // bitonic sort ascending over NTOK keys
    for (unsigned k = 2; k <= NTOK; k <<= 1) {
        for (unsigned j = k >> 1; j > 0; j >>= 1) {
            #pragma unroll
            for (int w = 0; w < 8; w++) {
                unsigned i  = tid + w * 1024;
                unsigned ix = i ^ j;
                if (ix > i) {
                    unsigned long long va = keys[i];
                    unsigned long long vb = keys[ix];
                    bool up = ((i & k) == 0);
                    if (up ? (va > vb) : (va < vb)) {
                        keys[i] = vb; keys[ix] = va;
                    }
                }
            }
            __syncthreads();
        }
    }

    if (tid < NUMHEAVY)
        sel[bt * NUMHEAVY + tid] = (int)(keys[tid] & 0xffffffffu);
}

// ---------------------------------------------------------------------------
// Fused GEMM: C[M,N] = act( A'[M,K] @ W[N,K]^T + bias )
// MODE 0: A = rmsnorm(x)*gamma (all tokens)    -> gelu -> hidden
// MODE 1: A = rmsnorm(x[sel])*gamma (gathered) -> gelu -> hidden
// MODE 2: A = hidden                           ->       C = v        (light out)
// MODE 3: A = hidden                           ->       C[sel] += v  (heavy scatter)
// 128x128 tile, 256 threads, 8x8 per thread, BK=8. All dims multiples of 128.
// ---------------------------------------------------------------------------
union F8 { float4 v[2]; float f[8]; };

template<int MODE>
__global__ __launch_bounds__(256)
void gemm_kernel(const float* __restrict__ Asrc,
                 const float* __restrict__ W,
                 const float* __restrict__ bias,
                 const float* __restrict__ scale,
                 const float* __restrict__ gamma,
                 const int*   __restrict__ sel,
                 float* __restrict__ C,
                 int M, int N, int K)
{
    __shared__ __align__(16) float As[8][128];
    __shared__ __align__(16) float Bs[8][128];
    __shared__ int   s_row[128];
    __shared__ float s_scl[128];
    __shared__ int   s_crow[128];

    const int tid = threadIdx.x;
    const int bx = blockIdx.x, by = blockIdx.y;

    if (tid < 128) {
        int m = by * 128 + tid;
        int arow = m; float sc = 1.0f; int crow = m;
        if (MODE == 0) {
            sc = scale[m];
        } else if (MODE == 1) {
            int t = sel[m];
            int g = (m >> 10) * NTOK + t;      // m/1024 = batch
            arow = g; sc = scale[g];
        } else if (MODE == 3) {
            int t = sel[m];
            crow = (m >> 10) * NTOK + t;
        }
        s_row[tid] = arow; s_scl[tid] = sc; s_crow[tid] = crow;
    }
    __syncthreads();

    float acc[8][8];
    #pragma unroll
    for (int i = 0; i < 8; i++)
        #pragma unroll
        for (int j = 0; j < 8; j++) acc[i][j] = 0.f;

    const int la_row = tid >> 1;          // 0..127
    const int la_k   = (tid & 1) * 4;     // 0 or 4
    const int tm0 = (tid >> 4) << 3;
    const int tn0 = (tid & 15) << 3;

    const size_t a_off = (size_t)s_row[la_row] * K + la_k;
    const float  a_s   = s_scl[la_row];
    const float* Wb = W + (size_t)(bx * 128 + la_row) * K + la_k;

    for (int k0 = 0; k0 < K; k0 += 8) {
        float4 av = *(const float4*)(Asrc + a_off + k0);
        if (MODE == 0 || MODE == 1) {
            float4 gv = *(const float4*)(gamma + k0 + la_k);
            av.x *= a_s * gv.x; av.y *= a_s * gv.y;
            av.z *= a_s * gv.z; av.w *= a_s * gv.w;
        }
        float4 wv = *(const float4*)(Wb + k0);
        As[la_k + 0][la_row] = av.x;
        As[la_k + 1][la_row] = av.y;
        As[la_k + 2][la_row] = av.z;
        As[la_k + 3][la_row] = av.w;
        Bs[la_k + 0][la_row] = wv.x;
        Bs[la_k + 1][la_row] = wv.y;
        Bs[la_k + 2][la_row] = wv.z;
        Bs[la_k + 3][la_row] = wv.w;
        __syncthreads();

        #pragma unroll
        for (int kk = 0; kk < 8; kk++) {
            F8 ar, br;
            ar.v[0] = *(const float4*)&As[kk][tm0];
            ar.v[1] = *(const float4*)&As[kk][tm0 + 4];
            br.v[0] = *(const float4*)&Bs[kk][tn0];
            br.v[1] = *(const float4*)&Bs[kk][tn0 + 4];
            #pragma unroll
            for (int i = 0; i < 8; i++)
                #pragma unroll
                for (int j = 0; j < 8; j++)
                    acc[i][j] += ar.f[i] * br.f[j];
        }
        __syncthreads();
    }

    #pragma unroll
    for (int i = 0; i < 8; i++) {
        int mloc = tm0 + i;
        #pragma unroll
        for (int j = 0; j < 8; j++) {
            int n = bx * 128 + tn0 + j;
            float v = acc[i][j] + bias[n];
            if (MODE == 0 || MODE == 1) {
                v = 0.5f * v * (1.0f + erff(v * 0.70710678118654752f));
                C[(size_t)(by * 128 + mloc) * N + n] = v;
            } else if (MODE == 2) {
                C[(size_t)(by * 128 + mloc) * N + n] = v;
            } else {
                size_t o = (size_t)s_crow[mloc] * N + n;
                C[o] += v;
            }
        }
    }
}

// ---------------------------------------------------------------------------
extern "C" void kernel_launch(void* const* d_in, const int* in_sizes, int n_in,
                              void* d_out, int out_size)
{
    const float* x       = (const float*)d_in[0];
    const float* rt      = (const float*)d_in[1];
    const float* gamma_l = (const float*)d_in[2];
    const float* w1_l    = (const float*)d_in[3];
    const float* b1_l    = (const float*)d_in[4];
    const float* w2_l    = (const float*)d_in[5];
    const float* b2_l    = (const float*)d_in[6];
    const float* gamma_h = (const float*)d_in[7];
    const float* w1_h    = (const float*)d_in[8];
    const float* b1_h    = (const float*)d_in[9];
    const float* w2_h    = (const float*)d_in[10];
    const float* b2_h    = (const float*)d_in[11];
    float* out = (float*)d_out;

    const int dim = in_sizes[1];   // 1024
    const int dl  = in_sizes[4];   // 512
    const int dh  = in_sizes[9];   // 4096

    float *p_s, *p_inv, *p_hid; int* p_sel;
    cudaGetSymbolAddress((void**)&p_s,   g_s);
    cudaGetSymbolAddress((void**)&p_inv, g_inv);
    cudaGetSymbolAddress((void**)&p_hid, g_hidden);
    cudaGetSymbolAddress((void**)&p_sel, g_sel);

    // 1. router logits + rmsnorm scales
    dot_norm_kernel<<<TOTT / 8, 256>>>(x, rt, p_s, p_inv, dim);

    // 2. coor_descent + top-k selection
    size_t smbytes = NTOK * sizeof(float) + NTOK * sizeof(unsigned long long) + 64 * sizeof(float);
    cudaFuncSetAttribute(router_kernel, cudaFuncAttributeMaxDynamicSharedMemorySize, (int)smbytes);
    float logk = logf(fminf((float)NUMHEAVY * (9.0f / 8.0f), (float)NTOK));
    router_kernel<<<BDIM, 1024, smbytes>>>(p_s, logk, p_sel);

    // 3. light FFN: gemm1+gelu -> hidden, gemm2 -> out
    {
        dim3 g1(dl / 128, TOTT / 128);
        gemm_kernel<0><<<g1, 256>>>(x, w1_l, b1_l, p_inv, gamma_l, nullptr, p_hid, TOTT, dl, dim);
        dim3 g2(dim / 128, TOTT / 128);
        gemm_kernel<2><<<g2, 256>>>(p_hid, w2_l, b2_l, nullptr, nullptr, nullptr, out, TOTT, dim, dl);
    }

    // 4. heavy FFN on gathered tokens: gemm1+gelu -> hidden (reuse), gemm2 scatter-add -> out
    {
        const int MH = BDIM * NUMHEAVY;            // 8192
        dim3 g1(dh / 128, MH / 128);
        gemm_kernel<1><<<g1, 256>>>(x, w1_h, b1_h, p_inv, gamma_h, p_sel, p_hid, MH, dh, dim);
        dim3 g2(dim / 128, MH / 128);
        gemm_kernel<3><<<g2, 256>>>(p_hid, w2_h, b2_h, nullptr, nullptr, p_sel, out, MH, dim, dh);
    }
}